// round 16
// baseline (speedup 1.0000x reference)
#include <cuda_runtime.h>
#include <cuda_fp16.h>
#include <cstdint>

#define BB 2
#define TQ 1024
#define TK 1024
#define DD 64
#define QW 4                 // queries per warp
#define WARPS 4
#define THREADS (WARPS * 32)
#define QT (WARPS * QW)      // 16 query rows per block
#define KT 32                // key tile (lane = key)
#define KSPLIT 8
#define KB (TK / KSPLIT)     // 128 keys per block
#define NT (KB / KT)         // 4 tiles
#define NROW (BB * TQ)
#define QGRID (TQ / QT)      // 64
#define VH_STRIDE 144        // 128B of half data + 16B pad (bank-conflict-free LDS.128)

__device__ float g_po[KSPLIT][NROW * DD];   // 4 MB
__device__ float g_pl[KSPLIT][NROW];        // 64 KB
__device__ int   g_cnt[BB][QGRID];          // zero-init; self-resetting

__device__ __forceinline__ __half2 tanh2h(__half2 x) {
    uint32_t xi = *(uint32_t*)&x, y;
    asm("tanh.approx.f16x2 %0, %1;" : "=r"(y) : "r"(xi));
    return *(__half2*)&y;
}

__device__ __forceinline__ void cp16(void* dst, const void* src) {
    unsigned d = (unsigned)__cvta_generic_to_shared(dst);
    asm volatile("cp.async.cg.shared.global [%0], [%1], 16;" :: "r"(d), "l"(src));
}
__device__ __forceinline__ void cp_commit() { asm volatile("cp.async.commit_group;"); }
template <int N>
__device__ __forceinline__ void cp_wait() { asm volatile("cp.async.wait_group %0;" :: "n"(N)); }

// raw V tile as float4 chunks, XOR-swizzled: chunk c of key k at k*16 + (c ^ (k&15))
__device__ __forceinline__ void prefetch_tile(float4* dst, const float4* V4, int tt, int tid) {
    #pragma unroll
    for (int i = 0; i < 4; i++) {
        int id = tid + i * THREADS;
        int k = id >> 4, c = id & 15;
        cp16(&dst[k * 16 + (c ^ (k & 15))], &V4[(size_t)tt * KT * 16 + k * 16 + c]);
    }
    cp_commit();
}

__global__ __launch_bounds__(THREADS, 4)
void addattn_kernel(const float* __restrict__ Q,
                    const float* __restrict__ V,
                    const float* __restrict__ S,
                    float* __restrict__ O) {
    __shared__ __align__(16) float4 v_s[3][KT * 16];        // 24 KB raw V ring
    __shared__ __align__(16) char   vh_s[KT * VH_STRIDE];   // 4.5 KB half2 V (current tile)
    __shared__ __align__(16) char   qh_s[QT * 128];         // 2 KB half2 Q
    __shared__ __align__(16) char   sch_s[128];             // half2 scale
    __shared__ __align__(16) float  p_s[2][KT][QT];         // 4 KB  [buf][key][query]
    __shared__ int s_last;

    const int tid  = threadIdx.x;
    const int lane = tid & 31;
    const int warp = tid >> 5;
    const int b    = blockIdx.y;
    const int ks   = blockIdx.z;
    const int q0   = blockIdx.x * QT;

    // ---- prologue: Q -> qh (half2), S -> sch (half2) ----
    const float4* Q4 = (const float4*)(Q + ((size_t)b * TQ + q0) * DD);
    #pragma unroll
    for (int i = 0; i < 2; i++) {
        int id = tid + i * THREADS;            // id = q*16 + c
        float4 u = Q4[id];
        __half2 h0 = __floats2half2_rn(u.x, u.y);
        __half2 h1 = __floats2half2_rn(u.z, u.w);
        uint2 w = make_uint2(*(uint32_t*)&h0, *(uint32_t*)&h1);
        *(uint2*)(qh_s + (id >> 4) * 128 + (id & 15) * 8) = w;
    }
    if (tid < 16) {
        float4 u = ((const float4*)S)[tid];
        __half2 h0 = __floats2half2_rn(u.x, u.y);
        __half2 h1 = __floats2half2_rn(u.z, u.w);
        uint2 w = make_uint2(*(uint32_t*)&h0, *(uint32_t*)&h1);
        *(uint2*)(sch_s + tid * 8) = w;
    }

    const float4* V4 = (const float4*)(V + ((size_t)b * TK + (size_t)ks * KB) * DD);
    prefetch_tile(v_s[0], V4, 0, tid);

    float l0 = 0.f, l1 = 0.f, l2 = 0.f, l3 = 0.f;
    float2 o0 = {0.f, 0.f}, o1 = {0.f, 0.f}, o2 = {0.f, 0.f}, o3 = {0.f, 0.f};
    const int c2   = lane >> 1, half = lane & 1;
    const int qa   = warp * QW;

    for (int t = 0; t < NT; ++t) {
        if (t > 0) __syncthreads();            // retire prior iter's reads (vh + raw(t-2))
        if (t + 1 < NT) {
            prefetch_tile(v_s[(t + 1) % 3], V4, t + 1, tid);
            cp_wait<1>();                      // raw(t) arrived, raw(t+1) in flight
        } else {
            cp_wait<0>();
        }
        __syncthreads();                       // raw(t) (+ prologue stores at t=0) visible

        // ---- build vh(t): raw f32 -> half2, 4 chunks per thread ----
        #pragma unroll
        for (int i = 0; i < 4; i++) {
            int id = tid + i * THREADS;        // id = k*16 + j
            int k = id >> 4, j = id & 15;
            float4 u = v_s[t % 3][k * 16 + (j ^ (k & 15))];
            __half2 h0 = __floats2half2_rn(u.x, u.y);
            __half2 h1 = __floats2half2_rn(u.z, u.w);
            uint2 w = make_uint2(*(uint32_t*)&h0, *(uint32_t*)&h1);
            *(uint2*)(vh_s + k * VH_STRIDE + j * 8) = w;
        }
        __syncthreads();                       // vh(t) visible

        const float4* vp = v_s[(t + 2) % 3];   // raw tile t-1 (phase-3)
        const int     pb = (t + 1) & 1;        // p buffer of tile t-1

        float2 a0 = {0.f, 0.f}, a1 = {0.f, 0.f}, a2 = {0.f, 0.f}, a3 = {0.f, 0.f};
        __half2 gs0, gs1, gs2, gs3;

        #pragma unroll
        for (int c = 0; c < 8; c++) {          // 8 dims per c-iter
            // --- phase 1 (tile t): half2 pipeline, lane = key ---
            uint4 vv = *(const uint4*)(vh_s + lane * VH_STRIDE + c * 16);
            uint4 ss = *(const uint4*)(sch_s + c * 16);
            __half2 v0 = *(__half2*)&vv.x, v1 = *(__half2*)&vv.y;
            __half2 v2 = *(__half2*)&vv.z, v3 = *(__half2*)&vv.w;
            __half2 s0 = *(__half2*)&ss.x, s1 = *(__half2*)&ss.y;
            __half2 s2 = *(__half2*)&ss.z, s3 = *(__half2*)&ss.w;

            #define SCORE_Q(qi, acc, gsv)                                          \
            {                                                                      \
                uint4 qq = *(const uint4*)(qh_s + (qa + qi) * 128 + c * 16);       \
                __half2 t0 = tanh2h(__hadd2(*(__half2*)&qq.x, v0));                \
                __half2 t1 = tanh2h(__hadd2(*(__half2*)&qq.y, v1));                \
                __half2 t2 = tanh2h(__hadd2(*(__half2*)&qq.z, v2));                \
                __half2 t3 = tanh2h(__hadd2(*(__half2*)&qq.w, v3));                \
                __half2 g0 = __hfma2(t1, s1, __hmul2(t0, s0));                     \
                __half2 g1 = __hfma2(t3, s3, __hmul2(t2, s2));                     \
                __half2 g  = __hadd2(g0, g1);                                      \
                if ((c & 1) == 0) { gsv = g; }                                     \
                else {                                                             \
                    float2 f = __half22float2(__hadd2(gsv, g));                    \
                    acc.x += f.x; acc.y += f.y;                                    \
                }                                                                  \
            }
            SCORE_Q(0, a0, gs0)
            SCORE_Q(1, a1, gs1)
            SCORE_Q(2, a2, gs2)
            SCORE_Q(3, a3, gs3)
            #undef SCORE_Q

            // --- phase 3 (tile t-1): keys 4c..4c+3, lane -> dims {2*lane, 2*lane+1} ---
            if (t > 0) {
                #pragma unroll
                for (int kk = 0; kk < 4; kk += 2) {
                    const int k0 = 4 * c + kk, k1 = 4 * c + kk + 1;
                    float4 pa = *(const float4*)&p_s[pb][k0][qa];
                    float4 pc = *(const float4*)&p_s[pb][k1][qa];
                    float2 va = ((const float2*)&vp[k0 * 16 + (c2 ^ (k0 & 15))])[half];
                    float2 vc = ((const float2*)&vp[k1 * 16 + (c2 ^ (k1 & 15))])[half];
                    o0.x = fmaf(pa.x, va.x, o0.x); o0.y = fmaf(pa.x, va.y, o0.y);
                    o1.x = fmaf(pa.y, va.x, o1.x); o1.y = fmaf(pa.y, va.y, o1.y);
                    o2.x = fmaf(pa.z, va.x, o2.x); o2.y = fmaf(pa.z, va.y, o2.y);
                    o3.x = fmaf(pa.w, va.x, o3.x); o3.y = fmaf(pa.w, va.y, o3.y);
                    o0.x = fmaf(pc.x, vc.x, o0.x); o0.y = fmaf(pc.x, vc.y, o0.y);
                    o1.x = fmaf(pc.y, vc.x, o1.x); o1.y = fmaf(pc.y, vc.y, o1.y);
                    o2.x = fmaf(pc.z, vc.x, o2.x); o2.y = fmaf(pc.z, vc.y, o2.y);
                    o3.x = fmaf(pc.w, vc.x, o3.x); o3.y = fmaf(pc.w, vc.y, o3.y);
                }
            }
        }

        float p0 = __expf(a0.x + a0.y), p1 = __expf(a1.x + a1.y);
        float p2 = __expf(a2.x + a2.y), p3 = __expf(a3.x + a3.y);
        l0 += p0; l1 += p1; l2 += p2; l3 += p3;
        *(float4*)&p_s[t & 1][lane][qa] = make_float4(p0, p1, p2, p3);
        __syncwarp();
    }

    // ---------- epilogue: phase 3 for tile NT-1 ----------
    {
        const float4* vp = v_s[(NT - 1) % 3];
        const int     pb = (NT - 1) & 1;
        #pragma unroll
        for (int c = 0; c < 16; c++) {
            const int k0 = 2 * c, k1 = 2 * c + 1;
            float4 pa = *(const float4*)&p_s[pb][k0][qa];
            float4 pc = *(const float4*)&p_s[pb][k1][qa];
            float2 va = ((const float2*)&vp[k0 * 16 + (c2 ^ (k0 & 15))])[half];
            float2 vc = ((const float2*)&vp[k1 * 16 + (c2 ^ (k1 & 15))])[half];
            o0.x = fmaf(pa.x, va.x, o0.x); o0.y = fmaf(pa.x, va.y, o0.y);
            o1.x = fmaf(pa.y, va.x, o1.x); o1.y = fmaf(pa.y, va.y, o1.y);
            o2.x = fmaf(pa.z, va.x, o2.x); o2.y = fmaf(pa.z, va.y, o2.y);
            o3.x = fmaf(pa.w, va.x, o3.x); o3.y = fmaf(pa.w, va.y, o3.y);
            o0.x = fmaf(pc.x, vc.x, o0.x); o0.y = fmaf(pc.x, vc.y, o0.y);
            o1.x = fmaf(pc.y, vc.x, o1.x); o1.y = fmaf(pc.y, vc.y, o1.y);
            o2.x = fmaf(pc.z, vc.x, o2.x); o2.y = fmaf(pc.z, vc.y, o2.y);
            o3.x = fmaf(pc.w, vc.x, o3.x); o3.y = fmaf(pc.w, vc.y, o3.y);
        }
    }

    // ---------- write unnormalized partials ----------
    #pragma unroll
    for (int off = 16; off > 0; off >>= 1) {
        l0 += __shfl_xor_sync(0xffffffffu, l0, off);
        l1 += __shfl_xor_sync(0xffffffffu, l1, off);
        l2 += __shfl_xor_sync(0xffffffffu, l2, off);
        l3 += __shfl_xor_sync(0xffffffffu, l3, off);
    }
    const int row0 = b * TQ + q0 + qa;
    ((float2*)&g_po[ks][(size_t)(row0 + 0) * DD])[lane] = o0;
    ((float2*)&g_po[ks][(size_t)(row0 + 1) * DD])[lane] = o1;
    ((float2*)&g_po[ks][(size_t)(row0 + 2) * DD])[lane] = o2;
    ((float2*)&g_po[ks][(size_t)(row0 + 3) * DD])[lane] = o3;
    if (lane == 0) {
        g_pl[ks][row0 + 0] = l0;
        g_pl[ks][row0 + 1] = l1;
        g_pl[ks][row0 + 2] = l2;
        g_pl[ks][row0 + 3] = l3;
    }

    // ---------- fused combine: single-thread release/acquire handshake ----------
    __syncthreads();
    if (tid == 0) {
        __threadfence();                       // release
        int old = atomicAdd(&g_cnt[b][blockIdx.x], 1);
        int last = (old == KSPLIT - 1) ? 1 : 0;
        if (last) __threadfence();             // acquire
        s_last = last;
    }
    __syncthreads();
    if (s_last) {
        #pragma unroll
        for (int i = 0; i < 2; i++) {
            const int id  = tid + i * THREADS;
            const int r   = id >> 4;
            const int d4  = id & 15;
            const int row = b * TQ + q0 + r;
            float l = 0.f;
            #pragma unroll
            for (int s = 0; s < KSPLIT; s++) l += g_pl[s][row];
            float4 acc = make_float4(0.f, 0.f, 0.f, 0.f);
            #pragma unroll
            for (int s = 0; s < KSPLIT; s++) {
                float4 v = ((const float4*)&g_po[s][(size_t)row * DD])[d4];
                acc.x += v.x; acc.y += v.y; acc.z += v.z; acc.w += v.w;
            }
            const float inv = 1.f / l;
            float4 rr; rr.x = acc.x * inv; rr.y = acc.y * inv;
            rr.z = acc.z * inv; rr.w = acc.w * inv;
            ((float4*)(O + (size_t)row * DD))[d4] = rr;
        }
        if (tid == 0) g_cnt[b][blockIdx.x] = 0;
    }
}

extern "C" void kernel_launch(void* const* d_in, const int* in_sizes, int n_in,
                              void* d_out, int out_size) {
    const float* Q = (const float*)d_in[0];
    const float* V = (const float*)d_in[1];
    const float* S = (const float*)d_in[2];
    float* O = (float*)d_out;
    dim3 grid(QGRID, BB, KSPLIT);              // 64 x 2 x 8 = 1024 blocks
    addattn_kernel<<<grid, THREADS>>>(Q, V, S, O);
}